// round 12
// baseline (speedup 1.0000x reference)
#include <cuda_runtime.h>

#define NV 8192
#define NC 4096
#define NB 512
#define NE 24576
#define NITER 5
#define EPSF 1e-12f
// clip = float(1 - 1e-7) = 1 - 2^-23.  Image of [-clip, clip] under (1+x)/(1-x):
#define RMAXF 16777215.0f      // = 2^24 - 1
#define RMINF 5.9604648e-8f    // = 1/(2^24 - 1) rounded

#define TPB 1024               // threads per CTA; one CTA = TWO batch elements (float2)
#define VPT (NV / TPB)         // 8 vars / thread
#define CPT (NC / TPB)         // 4 checks / thread
// smem: st planes float2[3][NV] (192KB) + P float2[NC] (32KB) = 229376 B (opt-in)
#define SMEM_BYTES ((3 * NV + NC) * 8)

// Graph structure (device globals: allocation-free per harness rules)
__device__ int      g_inv[NE];    // check -> 6 original edge ids (atomic build order)
__device__ int      g_cnt[NC];    // build counters
__device__ uint4    g_inv8[NC];   // 6 u16 slotted-st offsets per check (bank-scheduled slot order)
__device__ uint2    g_chk4[NV];   // 3 u16 check ids per var, in PLANE order (bank-scheduled)
__device__ unsigned g_eoff[NE];   // original edge id -> slotted st offset (plane*NV + v)

// ---------------------------------------------------------------- index build
__global__ void zero_cnt() {
    int i = blockIdx.x * blockDim.x + threadIdx.x;
    if (i < NC) g_cnt[i] = 0;
}

__global__ void build_inv(const int* __restrict__ chk) {
    int e = blockIdx.x * blockDim.x + threadIdx.x;
    if (e < NE) {
        int c = chk[e];
        int s = atomicAdd(&g_cnt[c], 1);
        g_inv[c * 6 + s] = e;
    }
}

// ---------------------------------------------------------------- var-side plane scheduling
// One thread per 32-var warp-group (vars v0..v0+31 are one warp-instruction in
// spa_kernel's var phase). Assign each var's 3 checks to planes 0..2 greedily so
// that each plane-slot's 32 P-gather addresses spread across the 16 bank-pairs.
// Writes g_chk4 (plane order) and g_eoff (orig edge -> plane-slotted st offset).
__global__ void var_assign(const int* __restrict__ chk) {
    int blk = blockIdx.x * blockDim.x + threadIdx.x;
    if (blk >= NV / 32) return;
    int v0 = blk * 32;

    int cs[32][3];
    int pick[32][3];              // pick[lane][k] = original j chosen for plane k
    bool used[32][3];
#pragma unroll
    for (int lane = 0; lane < 32; lane++) {
#pragma unroll
        for (int j = 0; j < 3; j++) {
            cs[lane][j] = chk[3 * (v0 + lane) + j];
            used[lane][j] = false;
        }
    }
    for (int k = 0; k < 3; k++) {
        int cnt[16];
#pragma unroll
        for (int b = 0; b < 16; b++) cnt[b] = 0;
        for (int lane = 0; lane < 32; lane++) {
            int best = -1, bc = 1 << 30;
            for (int j = 0; j < 3; j++) {
                if (used[lane][j]) continue;
                int b = cs[lane][j] & 15;          // bank-pair of s_P[c] (float2)
                if (cnt[b] < bc) { bc = cnt[b]; best = j; }
            }
            used[lane][best] = true;
            pick[lane][k] = best;
            cnt[cs[lane][best] & 15]++;
        }
    }
    for (int lane = 0; lane < 32; lane++) {
        int v = v0 + lane;
        unsigned c0 = (unsigned)cs[lane][pick[lane][0]];
        unsigned c1 = (unsigned)cs[lane][pick[lane][1]];
        unsigned c2 = (unsigned)cs[lane][pick[lane][2]];
        uint2 w; w.x = c0 | (c1 << 16); w.y = c2;
        g_chk4[v] = w;
#pragma unroll
        for (int k = 0; k < 3; k++)
            g_eoff[3 * v + pick[lane][k]] = (unsigned)(k * NV + v);
    }
}

// ---------------------------------------------------------------- check-side slot scheduling
// One thread per 32-check warp-group. Sort each check's 6 edges ascending
// (deterministic base order), map to plane-slotted offsets, then greedily order
// the 6 gather slots so each slot's 32 addresses spread across 16 bank-pairs.
__global__ void check_pack() {
    int blk = blockIdx.x * blockDim.x + threadIdx.x;
    if (blk >= NC / 32) return;
    int c0 = blk * 32;

    unsigned off[32][6];
    bool used[32][6];
    for (int lane = 0; lane < 32; lane++) {
        int a[6];
#pragma unroll
        for (int k = 0; k < 6; k++) a[k] = g_inv[(c0 + lane) * 6 + k];
#pragma unroll
        for (int x = 1; x < 6; x++)
#pragma unroll
            for (int j = x; j > 0; j--)
                if (a[j] < a[j - 1]) { int t = a[j]; a[j] = a[j - 1]; a[j - 1] = t; }
#pragma unroll
        for (int k = 0; k < 6; k++) {
            off[lane][k] = g_eoff[a[k]];
            used[lane][k] = false;
        }
    }
    unsigned slot[32][6];
    for (int k = 0; k < 6; k++) {
        int cnt[16];
#pragma unroll
        for (int b = 0; b < 16; b++) cnt[b] = 0;
        for (int lane = 0; lane < 32; lane++) {
            int best = -1, bc = 1 << 30;
            for (int j = 0; j < 6; j++) {
                if (used[lane][j]) continue;
                int b = (int)(off[lane][j] & 15);  // bank-pair of s_st[o] (float2)
                if (cnt[b] < bc) { bc = cnt[b]; best = j; }
            }
            used[lane][best] = true;
            slot[lane][k] = off[lane][best];
            cnt[off[lane][best] & 15]++;
        }
    }
    for (int lane = 0; lane < 32; lane++) {
        uint4 w;
        w.x = slot[lane][0] | (slot[lane][1] << 16);
        w.y = slot[lane][2] | (slot[lane][3] << 16);
        w.z = slot[lane][4] | (slot[lane][5] << 16);
        w.w = 0;
        g_inv8[c0 + lane] = w;
    }
}

// ---------------------------------------------------------------- helpers
__device__ __forceinline__ float tanh_half_from_exp(float el) {
    float t = __fdividef(el - 1.0f, el + 1.0f);
    return t + copysignf(EPSF, t);
}

__device__ __forceinline__ float clamp_r(float r) {
    return fminf(fmaxf(r, RMINF), RMAXF);
}

__device__ __forceinline__ float2 r_pair(float2 st, float2 p) {
    float2 r;
    r.x = clamp_r(__fdividef(st.x + p.x, st.x - p.x));
    r.y = clamp_r(__fdividef(st.y + p.y, st.y - p.y));
    return r;
}

// ---------------------------------------------------------------- persistent per-batch-pair decoder
// One CTA decodes TWO batch elements entirely in shared memory (float2 lanes):
//   s_st[3*NV] : plane-slotted st — var v's edges at {v, NV+v, 2NV+v}
//   s_P[NC]    : per-check signed product of 6 st
// Gather tables are bank-scheduled so random LDS.64 conflict degree ~2-3 not ~5.
__global__ void __launch_bounds__(TPB, 1)
spa_kernel(const float* __restrict__ llr, float* __restrict__ out) {
    extern __shared__ float2 sm[];
    float2* s_st = sm;            // 3*NV float2
    float2* s_P  = sm + 3 * NV;   // NC float2

    int tid = threadIdx.x;
    int b0  = 2 * blockIdx.x;
    const float* llr0 = llr + (b0 + 0) * NV;
    const float* llr1 = llr + (b0 + 1) * NV;

    // iter-0 messages: msg = llr on all 3 edges of each var (contiguous float2 stores)
#pragma unroll
    for (int m = 0; m < VPT; m++) {
        int v = tid + m * TPB;
        float2 t;
        t.x = tanh_half_from_exp(__expf(llr0[v]));
        t.y = tanh_half_from_exp(__expf(llr1[v]));
        s_st[v]          = t;
        s_st[NV + v]     = t;
        s_st[2 * NV + v] = t;
    }
    __syncthreads();

    for (int it = 0; it < NITER; it++) {
        // ---- check phase: P[c] = signed product of 6 st (bank-scheduled slot order)
#pragma unroll
        for (int m = 0; m < CPT; m++) {
            int c = tid + m * TPB;
            uint4 w = g_inv8[c];
            float2 a0 = s_st[w.x & 0xFFFF];
            float2 a1 = s_st[w.x >> 16];
            float2 a2 = s_st[w.y & 0xFFFF];
            float2 a3 = s_st[w.y >> 16];
            float2 a4 = s_st[w.z & 0xFFFF];
            float2 a5 = s_st[w.z >> 16];
            float2 p;
            p.x = ((((a0.x * a1.x) * a2.x) * a3.x) * a4.x) * a5.x;
            p.y = ((((a0.y * a1.y) * a2.y) * a3.y) * a4.y) * a5.y;
            s_P[c] = p;
        }
        __syncthreads();

        // ---- var phase: out(it) + next-iteration st
        int ob0 = it * (NB * NV) + (b0 + 0) * NV;
        int ob1 = it * (NB * NV) + (b0 + 1) * NV;
#pragma unroll
        for (int m = 0; m < VPT; m++) {
            int v = tid + m * TPB;
            float2 st0 = s_st[v];
            float2 st1 = s_st[NV + v];
            float2 st2 = s_st[2 * NV + v];
            uint2 cw = g_chk4[v];
            float2 p0 = s_P[cw.x & 0xFFFF];
            float2 p1 = s_P[cw.x >> 16];
            float2 p2 = s_P[cw.y];

            // r_e = e^{ext_e} = (st+P)/(st-P); signs cancel, r >= 0;
            // clamp is the exact image of the reference's loo clip.
            float2 r0 = r_pair(st0, p0);
            float2 r1 = r_pair(st1, p1);
            float2 r2 = r_pair(st2, p2);

            float l0 = llr0[v], l1 = llr1[v];
            out[ob0 + v] = l0 + __logf(r0.x * r1.x * r2.x);  // llr + sum of ext
            out[ob1 + v] = l1 + __logf(r0.y * r1.y * r2.y);

            if (it < NITER - 1) {
                // e^{msg_e} = e^llr * product of the OTHER two r's
                float e0 = __expf(l0), e1 = __expf(l1);
                float2 w0, w1, w2;
                w0.x = tanh_half_from_exp(e0 * (r1.x * r2.x));
                w0.y = tanh_half_from_exp(e1 * (r1.y * r2.y));
                w1.x = tanh_half_from_exp(e0 * (r0.x * r2.x));
                w1.y = tanh_half_from_exp(e1 * (r0.y * r2.y));
                w2.x = tanh_half_from_exp(e0 * (r0.x * r1.x));
                w2.y = tanh_half_from_exp(e1 * (r0.y * r1.y));
                s_st[v]          = w0;
                s_st[NV + v]     = w1;
                s_st[2 * NV + v] = w2;
            }
        }
        __syncthreads();
    }
}

// ---------------------------------------------------------------- launch
extern "C" void kernel_launch(void* const* d_in, const int* in_sizes, int n_in,
                              void* d_out, int out_size) {
    const float* llr = (const float*)d_in[0];
    // d_in[1] = var_index: structured as repeat(arange(NV), 3) -> not needed
    const int* chk = (const int*)d_in[2];
    float* out = (float*)d_out;

    cudaFuncSetAttribute(spa_kernel, cudaFuncAttributeMaxDynamicSharedMemorySize,
                         SMEM_BYTES);

    zero_cnt<<<(NC + 255) / 256, 256>>>();
    var_assign<<<(NV / 32 + 127) / 128, 128>>>(chk);
    build_inv<<<(NE + 255) / 256, 256>>>(chk);
    check_pack<<<(NC / 32 + 127) / 128, 128>>>();
    spa_kernel<<<NB / 2, TPB, SMEM_BYTES>>>(llr, out);
}

// round 13
// speedup vs baseline: 1.5842x; 1.5842x over previous
#include <cuda_runtime.h>

#define NV 8192
#define NC 4096
#define NB 512
#define NE 24576
#define NITER 5
#define EPSF 1e-12f
// clip = float(1 - 1e-7) = 1 - 2^-23.  Image of [-clip, clip] under (1+x)/(1-x):
#define RMAXF 16777215.0f      // = 2^24 - 1
#define RMINF 5.9604648e-8f    // = 1/(2^24 - 1) rounded

#define TPB 1024               // threads per CTA; one CTA = TWO batch elements (float2)
#define VPT (NV / TPB)         // 8 vars / thread
#define CPT (NC / TPB)         // 4 checks / thread
// smem: st planes float2[3][NV] (192KB) + P float2[NC] (32KB) = 229376 B (opt-in)
#define SMEM_BYTES ((3 * NV + NC) * 8)

// Graph structure (device globals: allocation-free per harness rules)
__device__ int      g_inv[NE];    // check -> 6 original edge ids (atomic build order)
__device__ int      g_cnt[NC];    // build counters
__device__ uint4    g_inv8[NC];   // 6 u16 slotted-st offsets per check (bank-scheduled slot order)
__device__ uint2    g_chk4[NV];   // 3 u16 check ids per var, in PLANE order (bank-scheduled)
__device__ unsigned g_eoff[NE];   // original edge id -> slotted st offset (plane*NV + v)

// ---------------------------------------------------------------- index build
__global__ void zero_cnt() {
    int i = blockIdx.x * blockDim.x + threadIdx.x;
    if (i < NC) g_cnt[i] = 0;
}

__global__ void build_inv(const int* __restrict__ chk) {
    int e = blockIdx.x * blockDim.x + threadIdx.x;
    if (e < NE) {
        int c = chk[e];
        int s = atomicAdd(&g_cnt[c], 1);
        g_inv[c * 6 + s] = e;
    }
}

// ---------------------------------------------------------------- var-side plane scheduling
// One WARP per 32-var group (lane = one var). Greedily assign each var's 3
// checks to planes 0..2 so each plane-slot's 32 P-gather addresses spread over
// the 16 float2 bank-pairs. Counters in per-warp smem; picks serialized over
// lanes (32 tiny steps), groups fully parallel across the chip.
__global__ void var_assign(const int* __restrict__ chk) {
    __shared__ int s_cnt[8][16];                 // 8 warps / 256-thread block
    int gwarp = (blockIdx.x * blockDim.x + threadIdx.x) >> 5;
    int lane  = threadIdx.x & 31;
    int wl    = (threadIdx.x >> 5) & 7;
    if (gwarp >= NV / 32) return;
    int v = gwarp * 32 + lane;

    int c[3];
#pragma unroll
    for (int j = 0; j < 3; j++) c[j] = chk[3 * v + j];
    unsigned used = 0;
    int pick[3];

#pragma unroll
    for (int k = 0; k < 3; k++) {
        if (lane < 16) s_cnt[wl][lane] = 0;
        __syncwarp();
        for (int i = 0; i < 32; i++) {
            if (lane == i) {
                int best = -1, bc = 1 << 30;
#pragma unroll
                for (int j = 0; j < 3; j++) {
                    if ((used >> j) & 1u) continue;
                    int b = c[j] & 15;           // bank-pair of s_P[c] (float2)
                    if (s_cnt[wl][b] < bc) { bc = s_cnt[wl][b]; best = j; }
                }
                used |= 1u << best;
                pick[k] = best;
                s_cnt[wl][c[best] & 15]++;
            }
            __syncwarp();
        }
    }
    uint2 w;
    w.x = (unsigned)c[pick[0]] | ((unsigned)c[pick[1]] << 16);
    w.y = (unsigned)c[pick[2]];
    g_chk4[v] = w;
#pragma unroll
    for (int k = 0; k < 3; k++)
        g_eoff[3 * v + pick[k]] = (unsigned)(k * NV + v);
}

// ---------------------------------------------------------------- check-side slot scheduling
// One WARP per 32-check group (lane = one check). Sort the 6 edges ascending
// (deterministic base product order), map to plane-slotted offsets, then greedily
// order the 6 gather slots to spread banks per slot.
__global__ void check_pack() {
    __shared__ int s_cnt[8][16];
    int gwarp = (blockIdx.x * blockDim.x + threadIdx.x) >> 5;
    int lane  = threadIdx.x & 31;
    int wl    = (threadIdx.x >> 5) & 7;
    if (gwarp >= NC / 32) return;
    int ch = gwarp * 32 + lane;

    int a[6];
#pragma unroll
    for (int k = 0; k < 6; k++) a[k] = g_inv[ch * 6 + k];
#pragma unroll
    for (int x = 1; x < 6; x++)
#pragma unroll
        for (int j = x; j > 0; j--)
            if (a[j] < a[j - 1]) { int t = a[j]; a[j] = a[j - 1]; a[j - 1] = t; }

    unsigned off[6];
#pragma unroll
    for (int k = 0; k < 6; k++) off[k] = g_eoff[a[k]];

    unsigned used = 0;
    unsigned slot[6];
#pragma unroll
    for (int k = 0; k < 6; k++) {
        if (lane < 16) s_cnt[wl][lane] = 0;
        __syncwarp();
        for (int i = 0; i < 32; i++) {
            if (lane == i) {
                int best = -1, bc = 1 << 30;
#pragma unroll
                for (int j = 0; j < 6; j++) {
                    if ((used >> j) & 1u) continue;
                    int b = (int)(off[j] & 15);  // bank-pair of s_st[o] (float2)
                    if (s_cnt[wl][b] < bc) { bc = s_cnt[wl][b]; best = j; }
                }
                used |= 1u << best;
                slot[k] = off[best];
                s_cnt[wl][off[best] & 15]++;
            }
            __syncwarp();
        }
    }
    uint4 w;
    w.x = slot[0] | (slot[1] << 16);
    w.y = slot[2] | (slot[3] << 16);
    w.z = slot[4] | (slot[5] << 16);
    w.w = 0;
    g_inv8[ch] = w;
}

// ---------------------------------------------------------------- helpers
__device__ __forceinline__ float tanh_half_from_exp(float el) {
    float t = __fdividef(el - 1.0f, el + 1.0f);
    return t + copysignf(EPSF, t);
}

__device__ __forceinline__ float clamp_r(float r) {
    return fminf(fmaxf(r, RMINF), RMAXF);
}

__device__ __forceinline__ float2 r_pair(float2 st, float2 p) {
    float2 r;
    r.x = clamp_r(__fdividef(st.x + p.x, st.x - p.x));
    r.y = clamp_r(__fdividef(st.y + p.y, st.y - p.y));
    return r;
}

// ---------------------------------------------------------------- persistent per-batch-pair decoder
// One CTA decodes TWO batch elements entirely in shared memory (float2 lanes):
//   s_st[3*NV] : plane-slotted st — var v's edges at {v, NV+v, 2NV+v}
//   s_P[NC]    : per-check signed product of 6 st
// Gather tables are bank-scheduled so random LDS.64 conflict degree ~2-3 not ~5.
__global__ void __launch_bounds__(TPB, 1)
spa_kernel(const float* __restrict__ llr, float* __restrict__ out) {
    extern __shared__ float2 sm[];
    float2* s_st = sm;            // 3*NV float2
    float2* s_P  = sm + 3 * NV;   // NC float2

    int tid = threadIdx.x;
    int b0  = 2 * blockIdx.x;
    const float* llr0 = llr + (b0 + 0) * NV;
    const float* llr1 = llr + (b0 + 1) * NV;

    // iter-0 messages: msg = llr on all 3 edges of each var (contiguous float2 stores)
#pragma unroll
    for (int m = 0; m < VPT; m++) {
        int v = tid + m * TPB;
        float2 t;
        t.x = tanh_half_from_exp(__expf(llr0[v]));
        t.y = tanh_half_from_exp(__expf(llr1[v]));
        s_st[v]          = t;
        s_st[NV + v]     = t;
        s_st[2 * NV + v] = t;
    }
    __syncthreads();

    for (int it = 0; it < NITER; it++) {
        // ---- check phase: P[c] = signed product of 6 st (bank-scheduled slot order)
#pragma unroll
        for (int m = 0; m < CPT; m++) {
            int c = tid + m * TPB;
            uint4 w = g_inv8[c];
            float2 a0 = s_st[w.x & 0xFFFF];
            float2 a1 = s_st[w.x >> 16];
            float2 a2 = s_st[w.y & 0xFFFF];
            float2 a3 = s_st[w.y >> 16];
            float2 a4 = s_st[w.z & 0xFFFF];
            float2 a5 = s_st[w.z >> 16];
            float2 p;
            p.x = ((((a0.x * a1.x) * a2.x) * a3.x) * a4.x) * a5.x;
            p.y = ((((a0.y * a1.y) * a2.y) * a3.y) * a4.y) * a5.y;
            s_P[c] = p;
        }
        __syncthreads();

        // ---- var phase: out(it) + next-iteration st
        int ob0 = it * (NB * NV) + (b0 + 0) * NV;
        int ob1 = it * (NB * NV) + (b0 + 1) * NV;
#pragma unroll
        for (int m = 0; m < VPT; m++) {
            int v = tid + m * TPB;
            float2 st0 = s_st[v];
            float2 st1 = s_st[NV + v];
            float2 st2 = s_st[2 * NV + v];
            uint2 cw = g_chk4[v];
            float2 p0 = s_P[cw.x & 0xFFFF];
            float2 p1 = s_P[cw.x >> 16];
            float2 p2 = s_P[cw.y];

            // r_e = e^{ext_e} = (st+P)/(st-P); signs cancel, r >= 0;
            // clamp is the exact image of the reference's loo clip.
            float2 r0 = r_pair(st0, p0);
            float2 r1 = r_pair(st1, p1);
            float2 r2 = r_pair(st2, p2);

            float l0 = llr0[v], l1 = llr1[v];
            out[ob0 + v] = l0 + __logf(r0.x * r1.x * r2.x);  // llr + sum of ext
            out[ob1 + v] = l1 + __logf(r0.y * r1.y * r2.y);

            if (it < NITER - 1) {
                // e^{msg_e} = e^llr * product of the OTHER two r's
                float e0 = __expf(l0), e1 = __expf(l1);
                float2 w0, w1, w2;
                w0.x = tanh_half_from_exp(e0 * (r1.x * r2.x));
                w0.y = tanh_half_from_exp(e1 * (r1.y * r2.y));
                w1.x = tanh_half_from_exp(e0 * (r0.x * r2.x));
                w1.y = tanh_half_from_exp(e1 * (r0.y * r2.y));
                w2.x = tanh_half_from_exp(e0 * (r0.x * r1.x));
                w2.y = tanh_half_from_exp(e1 * (r0.y * r1.y));
                s_st[v]          = w0;
                s_st[NV + v]     = w1;
                s_st[2 * NV + v] = w2;
            }
        }
        __syncthreads();
    }
}

// ---------------------------------------------------------------- launch
extern "C" void kernel_launch(void* const* d_in, const int* in_sizes, int n_in,
                              void* d_out, int out_size) {
    const float* llr = (const float*)d_in[0];
    // d_in[1] = var_index: structured as repeat(arange(NV), 3) -> not needed
    const int* chk = (const int*)d_in[2];
    float* out = (float*)d_out;

    cudaFuncSetAttribute(spa_kernel, cudaFuncAttributeMaxDynamicSharedMemorySize,
                         SMEM_BYTES);

    zero_cnt<<<(NC + 255) / 256, 256>>>();
    build_inv<<<(NE + 255) / 256, 256>>>(chk);
    var_assign<<<(NV / 32) * 32 / 256, 256>>>(chk);   // 256 warp-groups
    check_pack<<<(NC / 32) * 32 / 256, 256>>>();      // 128 warp-groups
    spa_kernel<<<NB / 2, TPB, SMEM_BYTES>>>(llr, out);
}